// round 6
// baseline (speedup 1.0000x reference)
#include <cuda_runtime.h>
#include <math.h>

#define B_BATCH 128
#define D_DIM   2048
#define P_DIM   16000
#define THREADS 1024

static __device__ int   g_idx[2 * D_DIM];
static __device__ float g_sgn[2 * D_DIM];

// ---------------------------------------------------------------------------
// Kernel 1: recover the sparse count-sketch (one +/-1 per row) from dense C.
// Branch-free moment reduction: sgn = sum(C[row,:]), idx = sgn * sum(p*C[row,p]).
// Exact in fp32 (idx < 2^14, all other terms are literal zeros).
// ---------------------------------------------------------------------------
#define EX_THREADS 512

__global__ void __launch_bounds__(EX_THREADS)
extract_kernel(const float* __restrict__ C1, const float* __restrict__ C2) {
    const int row = blockIdx.x;  // 0..4095
    const float4* b4 = (const float4*)((row < D_DIM)
                        ? (C1 + (size_t)row * P_DIM)
                        : (C2 + (size_t)(row - D_DIM) * P_DIM));
    float s = 0.0f, w = 0.0f;
#pragma unroll 4
    for (int i = threadIdx.x; i < P_DIM / 4; i += EX_THREADS) {
        float4 v = b4[i];
        float p0 = (float)(4 * i);
        float sv = (v.x + v.y) + (v.z + v.w);
        s += sv;
        w += p0 * sv + (v.y + 2.0f * v.z + 3.0f * v.w);
    }
#pragma unroll
    for (int o = 16; o > 0; o >>= 1) {
        s += __shfl_down_sync(0xFFFFFFFFu, s, o);
        w += __shfl_down_sync(0xFFFFFFFFu, w, o);
    }
    __shared__ float ss[EX_THREADS / 32], sw[EX_THREADS / 32];
    int lane = threadIdx.x & 31, warp = threadIdx.x >> 5;
    if (lane == 0) { ss[warp] = s; sw[warp] = w; }
    __syncthreads();
    if (warp == 0) {
        s = (lane < EX_THREADS / 32) ? ss[lane] : 0.0f;
        w = (lane < EX_THREADS / 32) ? sw[lane] : 0.0f;
#pragma unroll
        for (int o = EX_THREADS / 64; o > 0; o >>= 1) {
            s += __shfl_down_sync(0xFFFFFFFFu, s, o);
            w += __shfl_down_sync(0xFFFFFFFFu, w, o);
        }
        if (lane == 0) {
            g_sgn[row] = s;
            g_idx[row] = (int)rintf(w * s);
        }
    }
}

// base-5 digit reversal of 3 digits (involution), x in [0,125)
__device__ __forceinline__ int dr5(int x) {
    int a = x / 25;
    int rem = x - 25 * a;
    int b = rem / 5;
    int c = rem - 5 * b;
    return c * 25 + b * 5 + a;
}

typedef float2 cplx;
__device__ __forceinline__ cplx cmul(cplx a, cplx b) {
    return make_float2(a.x * b.x - a.y * b.y, a.x * b.y + a.y * b.x);
}
__device__ __forceinline__ cplx cmulc(cplx a, cplx b) {   // a * conj(b)
    return make_float2(a.x * b.x + a.y * b.y, a.y * b.x - a.x * b.y);
}
__device__ __forceinline__ cplx cadd(cplx a, cplx b) { return make_float2(a.x + b.x, a.y + b.y); }
__device__ __forceinline__ cplx csub(cplx a, cplx b) { return make_float2(a.x - b.x, a.y - b.y); }

#define C72  ( 0.30901699437494742f)
#define S72  ( 0.95105651629515357f)
#define C144 (-0.80901699437494745f)
#define S144 ( 0.58778525229247314f)

// 5-point butterfly, forward sign (e^-), in place, no twiddle.
__device__ __forceinline__ void bf5_fwd(cplx a[5]) {
    cplx t1 = cadd(a[1], a[4]), t3 = csub(a[1], a[4]);
    cplx t2 = cadd(a[2], a[3]), t4 = csub(a[2], a[3]);
    cplx a0 = a[0];
    cplx m1 = make_float2(a0.x + C72 * t1.x + C144 * t2.x, a0.y + C72 * t1.y + C144 * t2.y);
    cplx m2 = make_float2(a0.x + C144 * t1.x + C72 * t2.x, a0.y + C144 * t1.y + C72 * t2.y);
    cplx v1 = make_float2(S72 * t3.x + S144 * t4.x, S72 * t3.y + S144 * t4.y);
    cplx v2 = make_float2(S144 * t3.x - S72 * t4.x, S144 * t3.y - S72 * t4.y);
    a[0] = make_float2(a0.x + t1.x + t2.x, a0.y + t1.y + t2.y);
    a[1] = make_float2(m1.x + v1.y, m1.y - v1.x);
    a[2] = make_float2(m2.x + v2.y, m2.y - v2.x);
    a[3] = make_float2(m2.x - v2.y, m2.y + v2.x);
    a[4] = make_float2(m1.x - v1.y, m1.y + v1.x);
}

// 5-point butterfly, inverse sign (e^+), in place, no twiddle.
__device__ __forceinline__ void bf5_inv(cplx a[5]) {
    cplx t1 = cadd(a[1], a[4]), t3 = csub(a[1], a[4]);
    cplx t2 = cadd(a[2], a[3]), t4 = csub(a[2], a[3]);
    cplx a0 = a[0];
    cplx m1 = make_float2(a0.x + C72 * t1.x + C144 * t2.x, a0.y + C72 * t1.y + C144 * t2.y);
    cplx m2 = make_float2(a0.x + C144 * t1.x + C72 * t2.x, a0.y + C144 * t1.y + C72 * t2.y);
    cplx v1 = make_float2(S72 * t3.x + S144 * t4.x, S72 * t3.y + S144 * t4.y);
    cplx v2 = make_float2(S144 * t3.x - S72 * t4.x, S144 * t3.y - S72 * t4.y);
    a[0] = make_float2(a0.x + t1.x + t2.x, a0.y + t1.y + t2.y);
    a[1] = make_float2(m1.x - v1.y, m1.y + v1.x);
    a[2] = make_float2(m2.x - v2.y, m2.y + v2.x);
    a[3] = make_float2(m2.x + v2.y, m2.y - v2.x);
    a[4] = make_float2(m1.x + v1.y, m1.y - v1.x);
}

// Radix-8 DIT (3 merged radix-2 DIT stages).
__device__ __forceinline__ void radix8_dit(cplx x[8], int j, const cplx* t128) {
    cplx wa = t128[8 * j];
#pragma unroll
    for (int t = 0; t < 8; t += 2) {
        cplx v = cmul(x[t + 1], wa);
        x[t + 1] = csub(x[t], v);
        x[t]     = cadd(x[t], v);
    }
    cplx wb0 = t128[4 * j];
    cplx wb1 = t128[4 * j + 32];
#pragma unroll
    for (int q = 0; q < 2; q++) {
        int b0 = 4 * q;
        {
            cplx v = cmul(x[b0 + 2], wb0);
            x[b0 + 2] = csub(x[b0], v);
            x[b0]     = cadd(x[b0], v);
        }
        {
            cplx v = cmul(x[b0 + 3], wb1);
            x[b0 + 3] = csub(x[b0 + 1], v);
            x[b0 + 1] = cadd(x[b0 + 1], v);
        }
    }
#pragma unroll
    for (int t = 0; t < 4; t++) {
        cplx w = t128[2 * j + 16 * t];
        cplx v = cmul(x[t + 4], w);
        x[t + 4] = csub(x[t], v);
        x[t]     = cadd(x[t], v);
    }
}

// Radix-8 DIF (3 merged radix-2 DIF stages, inverse direction = conj twiddles).
__device__ __forceinline__ void radix8_dif(cplx x[8], int j, const cplx* t128) {
#pragma unroll
    for (int t = 0; t < 4; t++) {
        cplx w = t128[2 * j + 16 * t];
        cplx u = x[t], v = x[t + 4];
        x[t]     = cadd(u, v);
        x[t + 4] = cmulc(csub(u, v), w);
    }
    cplx wb0 = t128[4 * j];
    cplx wb1 = t128[4 * j + 32];
#pragma unroll
    for (int q = 0; q < 2; q++) {
        int b0 = 4 * q;
        {
            cplx u = x[b0], v = x[b0 + 2];
            x[b0]     = cadd(u, v);
            x[b0 + 2] = cmulc(csub(u, v), wb0);
        }
        {
            cplx u = x[b0 + 1], v = x[b0 + 3];
            x[b0 + 1] = cadd(u, v);
            x[b0 + 3] = cmulc(csub(u, v), wb1);
        }
    }
    cplx wa = t128[8 * j];
#pragma unroll
    for (int t = 0; t < 8; t += 2) {
        cplx u = x[t], v = x[t + 1];
        x[t]     = cadd(u, v);
        x[t + 1] = cmulc(csub(u, v), wa);
    }
}

// ---------------------------------------------------------------------------
// Kernel 2: warp-ownership four-step FFT.
//   radix-2 half: column-local  -> warp owns columns {w, w+32, w+64, w+96}
//   radix-5 half: row-local     -> warp owns rows    {4w .. 4w+3}
// Only 6 block-wide barriers; everything else is __syncwarp().
// ---------------------------------------------------------------------------
__global__ void __launch_bounds__(THREADS)
mcb_fft_kernel(const float* __restrict__ x1, const float* __restrict__ x2,
               float* __restrict__ out) {
    extern __shared__ cplx S[];                // 16000 complex = 128000 B
    __shared__ cplx t128[128];                 // e^{-2pi i t/128}
    __shared__ cplx t125[125];                 // e^{-2pi i t/125}
    __shared__ cplx tS[125];                   // e^{-2pi i t/16000}

    const int tid  = threadIdx.x;
    const int lane = tid & 31;
    const int w    = tid >> 5;                 // warp id, 0..31
    const int b    = blockIdx.x;
    const double TWO_PI = 6.283185307179586476925286766559;

    for (int t = tid; t < 128; t += THREADS) {
        double s, c; sincos(-TWO_PI * (double)t / 128.0, &s, &c);
        t128[t] = make_float2((float)c, (float)s);
    }
    for (int t = tid; t < 125; t += THREADS) {
        double s, c;
        sincos(-TWO_PI * (double)t / 125.0, &s, &c);
        t125[t] = make_float2((float)c, (float)s);
        sincos(-TWO_PI * (double)t / 16000.0, &s, &c);
        tS[t] = make_float2((float)c, (float)s);
    }
    for (int i = tid; i < P_DIM; i += THREADS) S[i] = make_float2(0.0f, 0.0f);
    __syncthreads();                                              // B1

    // scatter: y1 -> real, y2 -> imag, rows bit-reversed for the DIT stages
    for (int d = tid; d < D_DIM; d += THREADS) {
        int p = g_idx[d];
        float v = x1[b * D_DIM + d] * g_sgn[d];
        int n1 = p / 125, n2 = p - n1 * 125;
        int r = __brev(n1) >> 25;
        atomicAdd(&S[r * 125 + n2].x, v);
        p = g_idx[D_DIM + d];
        v = x2[b * D_DIM + d] * g_sgn[D_DIM + d];
        n1 = p / 125; n2 = p - n1 * 125;
        r = __brev(n1) >> 25;
        atomicAdd(&S[r * 125 + n2].y, v);
    }
    __syncthreads();                                              // B2

    const int ncol = (w < 29) ? 4 : 3;        // columns w+32k < 125

    // ======== forward radix-2 half (column-local, warp-synced) ========
    // pass A: stages 0..2  (rows 8g+t, stride 125)
    for (int item = lane; item < ncol * 16; item += 32) {
        int c = w + 32 * (item >> 4);
        int g = item & 15;
        int base = g * 1000 + c;
        cplx x[8];
#pragma unroll
        for (int t = 0; t < 8; t++) x[t] = S[base + t * 125];
        radix8_dit(x, 0, t128);
#pragma unroll
        for (int t = 0; t < 8; t++) S[base + t * 125] = x[t];
    }
    __syncwarp();
    // pass B: stages 3..5  (rows 64u + j + 8t, stride 1000)
    for (int item = lane; item < ncol * 16; item += 32) {
        int c = w + 32 * (item >> 4);
        int g = item & 15;
        int u = g >> 3, j = g & 7;
        int base = (u * 64 + j) * 125 + c;
        cplx x[8];
#pragma unroll
        for (int t = 0; t < 8; t++) x[t] = S[base + t * 1000];
        radix8_dit(x, j, t128);
#pragma unroll
        for (int t = 0; t < 8; t++) S[base + t * 1000] = x[t];
    }
    __syncwarp();
    // pass C: stage 6 fused with inter-phase twiddle w^{c*k1}
    for (int item = lane; item < ncol * 64; item += 32) {
        int c = w + 32 * (item >> 6);
        int r = item & 63;
        int p0 = r * 125 + c;
        int p1 = p0 + 8000;
        cplx u = S[p0];
        cplx v = cmul(S[p1], t128[r]);
        cplx X0 = cadd(u, v);
        cplx X1 = csub(u, v);
        int mm = c * r;
        int q = mm / 125, rr = mm - q * 125;
        S[p0] = cmul(X0, cmul(t128[q], tS[rr]));
        int mm2 = mm + 64 * c;
        q = mm2 / 125; rr = mm2 - q * 125;
        S[p1] = cmul(X1, cmul(t128[q], tS[rr]));
    }
    __syncthreads();                                              // B3

    // ======== forward radix-5 half (row-local, warp owns rows 4w..4w+3) ====
    // stage 0: L=125, m=25, twiddle index q*bj
    for (int item = lane; item < 100; item += 32) {
        int row = 4 * w + item / 25;
        int bj  = item % 25;
        int base = row * 125 + bj;
        cplx a[5];
#pragma unroll
        for (int q = 0; q < 5; q++) a[q] = S[base + q * 25];
        bf5_fwd(a);
        S[base] = a[0];
#pragma unroll
        for (int q = 1; q < 5; q++) S[base + q * 25] = cmul(a[q], t125[q * bj]);
    }
    __syncwarp();
    // stage 1: L=25, m=5, twiddle index q*5*(bj%5)
    for (int item = lane; item < 100; item += 32) {
        int row = 4 * w + item / 25;
        int bj  = item % 25;
        int j = bj % 5, grp = bj / 5;
        int base = row * 125 + grp * 25 + j;
        int jf = j * 5;
        cplx a[5];
#pragma unroll
        for (int q = 0; q < 5; q++) a[q] = S[base + q * 5];
        bf5_fwd(a);
        S[base] = a[0];
#pragma unroll
        for (int q = 1; q < 5; q++) S[base + q * 5] = cmul(a[q], t125[q * jf]);
    }
    __syncwarp();
    // stage 2: L=5, m=1, trivial twiddles
    for (int item = lane; item < 100; item += 32) {
        int row = 4 * w + item / 25;
        int bj  = item % 25;
        int base = row * 125 + bj * 5;
        cplx a[5];
#pragma unroll
        for (int q = 0; q < 5; q++) a[q] = S[base + q];
        bf5_fwd(a);
#pragma unroll
        for (int q = 0; q < 5; q++) S[base + q] = a[q];
    }
    __syncthreads();                                              // B4

    // ======== Hermitian split + pointwise multiply (block-wide) ========
    for (int k = tid; k <= 8000; k += THREADS) {
        if (k == 0) {
            cplx z = S[0];
            S[0] = make_float2(z.x * z.y, 0.0f);
        } else if (k == 8000) {
            const int addr = 64 * 125 + 62;
            cplx z = S[addr];
            S[addr] = make_float2(z.x * z.y, 0.0f);
        } else {
            int k1 = k & 127, k2 = k >> 7;
            int pa = k1 * 125 + dr5(k2);
            int kp = P_DIM - k;
            int k1p = kp & 127, k2p = kp >> 7;
            int pb = k1p * 125 + dr5(k2p);
            cplx A = S[pa];
            cplx Bv = S[pb];
            float F1r = 0.5f * (A.x + Bv.x), F1i = 0.5f * (A.y - Bv.y);
            float F2r = 0.5f * (A.y + Bv.y), F2i = 0.5f * (Bv.x - A.x);
            float Hr = F1r * F2r - F1i * F2i;
            float Hi = F1r * F2i + F1i * F2r;
            S[pa] = make_float2(Hr,  Hi);
            S[pb] = make_float2(Hr, -Hi);
        }
    }
    __syncthreads();                                              // B5

    // ======== inverse radix-5 half (row-local) ========
    // stage 0: L=5, m=1, trivial twiddles
    for (int item = lane; item < 100; item += 32) {
        int row = 4 * w + item / 25;
        int bj  = item % 25;
        int base = row * 125 + bj * 5;
        cplx a[5];
#pragma unroll
        for (int q = 0; q < 5; q++) a[q] = S[base + q];
        bf5_inv(a);
#pragma unroll
        for (int q = 0; q < 5; q++) S[base + q] = a[q];
    }
    __syncwarp();
    // stage 1: L=25, m=5
    for (int item = lane; item < 100; item += 32) {
        int row = 4 * w + item / 25;
        int bj  = item % 25;
        int j = bj % 5, grp = bj / 5;
        int base = row * 125 + grp * 25 + j;
        int jf = j * 5;
        cplx a[5];
        a[0] = S[base];
#pragma unroll
        for (int q = 1; q < 5; q++) a[q] = cmulc(S[base + q * 5], t125[q * jf]);
        bf5_inv(a);
#pragma unroll
        for (int q = 0; q < 5; q++) S[base + q * 5] = a[q];
    }
    __syncwarp();
    // stage 2: L=125, m=25
    for (int item = lane; item < 100; item += 32) {
        int row = 4 * w + item / 25;
        int bj  = item % 25;
        int base = row * 125 + bj;
        cplx a[5];
        a[0] = S[base];
#pragma unroll
        for (int q = 1; q < 5; q++) a[q] = cmulc(S[base + q * 25], t125[q * bj]);
        bf5_inv(a);
#pragma unroll
        for (int q = 0; q < 5; q++) S[base + q * 25] = a[q];
    }
    __syncthreads();                                              // B6

    // ======== inverse radix-2 half (column-local) ========
    // pass C': inter-phase conj twiddle fused with stage 6
    for (int item = lane; item < ncol * 64; item += 32) {
        int c = w + 32 * (item >> 6);
        int r = item & 63;
        int p0 = r * 125 + c;
        int p1 = p0 + 8000;
        int mm = c * r;
        int q = mm / 125, rr = mm - q * 125;
        cplx u = cmulc(S[p0], cmul(t128[q], tS[rr]));
        int mm2 = mm + 64 * c;
        q = mm2 / 125; rr = mm2 - q * 125;
        cplx v = cmulc(S[p1], cmul(t128[q], tS[rr]));
        S[p0] = cadd(u, v);
        S[p1] = cmulc(csub(u, v), t128[r]);
    }
    __syncwarp();
    // pass B': stages 5..3
    for (int item = lane; item < ncol * 16; item += 32) {
        int c = w + 32 * (item >> 4);
        int g = item & 15;
        int u = g >> 3, j = g & 7;
        int base = (u * 64 + j) * 125 + c;
        cplx x[8];
#pragma unroll
        for (int t = 0; t < 8; t++) x[t] = S[base + t * 1000];
        radix8_dif(x, j, t128);
#pragma unroll
        for (int t = 0; t < 8; t++) S[base + t * 1000] = x[t];
    }
    __syncwarp();
    // pass A': stages 2..0 fused with output write (real part / N)
    const float scale = 1.0f / 16000.0f;
    for (int item = lane; item < ncol * 16; item += 32) {
        int c = w + 32 * (item >> 4);
        int g = item & 15;
        int base = g * 1000 + c;
        cplx x[8];
#pragma unroll
        for (int t = 0; t < 8; t++) x[t] = S[base + t * 125];
        radix8_dif(x, 0, t128);
#pragma unroll
        for (int t = 0; t < 8; t++) {
            int n1 = __brev(8 * g + t) >> 25;
            out[b * P_DIM + n1 * 125 + c] = x[t].x * scale;
        }
    }
}

extern "C" void kernel_launch(void* const* d_in, const int* in_sizes, int n_in,
                              void* d_out, int out_size) {
    const float* x1 = (const float*)d_in[0];
    const float* x2 = (const float*)d_in[1];
    const float* C1 = (const float*)d_in[2];
    const float* C2 = (const float*)d_in[3];
    float* out = (float*)d_out;

    extract_kernel<<<2 * D_DIM, EX_THREADS>>>(C1, C2);

    const size_t smem = (size_t)P_DIM * sizeof(cplx);  // 128000 B
    cudaFuncSetAttribute(mcb_fft_kernel,
                         cudaFuncAttributeMaxDynamicSharedMemorySize, (int)smem);
    mcb_fft_kernel<<<B_BATCH, THREADS, smem>>>(x1, x2, out);
}

// round 7
// speedup vs baseline: 1.8395x; 1.8395x over previous
#include <cuda_runtime.h>
#include <math.h>

#define B_BATCH 128
#define D_DIM   2048
#define P_DIM   16000
#define THREADS 1024

static __device__ int   g_idx[2 * D_DIM];
static __device__ float g_sgn[2 * D_DIM];

// ---------------------------------------------------------------------------
// Kernel 1: recover the sparse count-sketch (one +/-1 per row) from dense C.
// Branch-free moment reduction: sgn = sum(C[row,:]), idx = sgn * sum(p*C[row,p]).
// Exact in fp32 (idx < 2^14, all other terms are literal zeros).
// ---------------------------------------------------------------------------
#define EX_THREADS 512

__global__ void __launch_bounds__(EX_THREADS)
extract_kernel(const float* __restrict__ C1, const float* __restrict__ C2) {
    const int row = blockIdx.x;  // 0..4095
    const float4* b4 = (const float4*)((row < D_DIM)
                        ? (C1 + (size_t)row * P_DIM)
                        : (C2 + (size_t)(row - D_DIM) * P_DIM));
    float s = 0.0f, w = 0.0f;
#pragma unroll 4
    for (int i = threadIdx.x; i < P_DIM / 4; i += EX_THREADS) {
        float4 v = b4[i];
        float p0 = (float)(4 * i);
        float sv = (v.x + v.y) + (v.z + v.w);
        s += sv;
        w += p0 * sv + (v.y + 2.0f * v.z + 3.0f * v.w);
    }
#pragma unroll
    for (int o = 16; o > 0; o >>= 1) {
        s += __shfl_down_sync(0xFFFFFFFFu, s, o);
        w += __shfl_down_sync(0xFFFFFFFFu, w, o);
    }
    __shared__ float ss[EX_THREADS / 32], sw[EX_THREADS / 32];
    int lane = threadIdx.x & 31, warp = threadIdx.x >> 5;
    if (lane == 0) { ss[warp] = s; sw[warp] = w; }
    __syncthreads();
    if (warp == 0) {
        s = (lane < EX_THREADS / 32) ? ss[lane] : 0.0f;
        w = (lane < EX_THREADS / 32) ? sw[lane] : 0.0f;
#pragma unroll
        for (int o = EX_THREADS / 64; o > 0; o >>= 1) {
            s += __shfl_down_sync(0xFFFFFFFFu, s, o);
            w += __shfl_down_sync(0xFFFFFFFFu, w, o);
        }
        if (lane == 0) {
            g_sgn[row] = s;
            g_idx[row] = (int)rintf(w * s);
        }
    }
}

// base-5 digit reversal of 3 digits (involution), x in [0,125)
__device__ __forceinline__ int dr5(int x) {
    int a = x / 25;
    int rem = x - 25 * a;
    int b = rem / 5;
    int c = rem - 5 * b;
    return c * 25 + b * 5 + a;
}

typedef float2 cplx;
__device__ __forceinline__ cplx cmul(cplx a, cplx b) {
    return make_float2(a.x * b.x - a.y * b.y, a.x * b.y + a.y * b.x);
}
__device__ __forceinline__ cplx cmulc(cplx a, cplx b) {   // a * conj(b)
    return make_float2(a.x * b.x + a.y * b.y, a.y * b.x - a.x * b.y);
}
__device__ __forceinline__ cplx cadd(cplx a, cplx b) { return make_float2(a.x + b.x, a.y + b.y); }
__device__ __forceinline__ cplx csub(cplx a, cplx b) { return make_float2(a.x - b.x, a.y - b.y); }

// Radix-8 DIT (3 merged radix-2 DIT stages 0..2, j = 0 here always).
__device__ __forceinline__ void radix8_dit(cplx x[8], int j, const cplx* t128) {
    cplx wa = t128[8 * j];
#pragma unroll
    for (int t = 0; t < 8; t += 2) {
        cplx v = cmul(x[t + 1], wa);
        x[t + 1] = csub(x[t], v);
        x[t]     = cadd(x[t], v);
    }
    cplx wb0 = t128[4 * j];
    cplx wb1 = t128[4 * j + 32];
#pragma unroll
    for (int q = 0; q < 2; q++) {
        int b0 = 4 * q;
        {
            cplx v = cmul(x[b0 + 2], wb0);
            x[b0 + 2] = csub(x[b0], v);
            x[b0]     = cadd(x[b0], v);
        }
        {
            cplx v = cmul(x[b0 + 3], wb1);
            x[b0 + 3] = csub(x[b0 + 1], v);
            x[b0 + 1] = cadd(x[b0 + 1], v);
        }
    }
#pragma unroll
    for (int t = 0; t < 4; t++) {
        cplx w = t128[2 * j + 16 * t];
        cplx v = cmul(x[t + 4], w);
        x[t + 4] = csub(x[t], v);
        x[t]     = cadd(x[t], v);
    }
}

// Radix-8 DIF (inverse stages 2..0, conj twiddles).
__device__ __forceinline__ void radix8_dif(cplx x[8], int j, const cplx* t128) {
#pragma unroll
    for (int t = 0; t < 4; t++) {
        cplx w = t128[2 * j + 16 * t];
        cplx u = x[t], v = x[t + 4];
        x[t]     = cadd(u, v);
        x[t + 4] = cmulc(csub(u, v), w);
    }
    cplx wb0 = t128[4 * j];
    cplx wb1 = t128[4 * j + 32];
#pragma unroll
    for (int q = 0; q < 2; q++) {
        int b0 = 4 * q;
        {
            cplx u = x[b0], v = x[b0 + 2];
            x[b0]     = cadd(u, v);
            x[b0 + 2] = cmulc(csub(u, v), wb0);
        }
        {
            cplx u = x[b0 + 1], v = x[b0 + 3];
            x[b0 + 1] = cadd(u, v);
            x[b0 + 3] = cmulc(csub(u, v), wb1);
        }
    }
    cplx wa = t128[8 * j];
#pragma unroll
    for (int t = 0; t < 8; t += 2) {
        cplx u = x[t], v = x[t + 1];
        x[t]     = cadd(u, v);
        x[t + 1] = cmulc(csub(u, v), wa);
    }
}

// Radix-16 DIT: radix-2 stages 3..6 on x[t] = row (j + 8t), j in [0,8).
__device__ __forceinline__ void radix16_dit(cplx x[16], int j, const cplx* t128) {
    // stage 3: pairs (t, t+1) even t, twiddle t128[8j]
    cplx wa = t128[8 * j];
#pragma unroll
    for (int t = 0; t < 16; t += 2) {
        cplx v = cmul(x[t + 1], wa);
        x[t + 1] = csub(x[t], v);
        x[t]     = cadd(x[t], v);
    }
    // stage 4: pairs (t, t+2), twiddles t128[4j], t128[4j+32]
    cplx wb0 = t128[4 * j];
    cplx wb1 = t128[4 * j + 32];
#pragma unroll
    for (int b0 = 0; b0 < 16; b0 += 4) {
        {
            cplx v = cmul(x[b0 + 2], wb0);
            x[b0 + 2] = csub(x[b0], v);
            x[b0]     = cadd(x[b0], v);
        }
        {
            cplx v = cmul(x[b0 + 3], wb1);
            x[b0 + 3] = csub(x[b0 + 1], v);
            x[b0 + 1] = cadd(x[b0 + 1], v);
        }
    }
    // stage 5: pairs (grp+q, grp+q+4), grp in {0,8}, twiddle t128[2j+16q]
#pragma unroll
    for (int grp = 0; grp < 16; grp += 8) {
#pragma unroll
        for (int q = 0; q < 4; q++) {
            cplx w = t128[2 * j + 16 * q];
            cplx v = cmul(x[grp + q + 4], w);
            x[grp + q + 4] = csub(x[grp + q], v);
            x[grp + q]     = cadd(x[grp + q], v);
        }
    }
    // stage 6: pairs (t, t+8), twiddle t128[j+8t]
#pragma unroll
    for (int t = 0; t < 8; t++) {
        cplx w = t128[j + 8 * t];
        cplx v = cmul(x[t + 8], w);
        x[t + 8] = csub(x[t], v);
        x[t]     = cadd(x[t], v);
    }
}

// Radix-16 DIF: inverse stages 6..3 with conj twiddles.
__device__ __forceinline__ void radix16_dif(cplx x[16], int j, const cplx* t128) {
    // stage 6'
#pragma unroll
    for (int t = 0; t < 8; t++) {
        cplx w = t128[j + 8 * t];
        cplx u = x[t], v = x[t + 8];
        x[t]     = cadd(u, v);
        x[t + 8] = cmulc(csub(u, v), w);
    }
    // stage 5'
#pragma unroll
    for (int grp = 0; grp < 16; grp += 8) {
#pragma unroll
        for (int q = 0; q < 4; q++) {
            cplx w = t128[2 * j + 16 * q];
            cplx u = x[grp + q], v = x[grp + q + 4];
            x[grp + q]     = cadd(u, v);
            x[grp + q + 4] = cmulc(csub(u, v), w);
        }
    }
    // stage 4'
    cplx wb0 = t128[4 * j];
    cplx wb1 = t128[4 * j + 32];
#pragma unroll
    for (int b0 = 0; b0 < 16; b0 += 4) {
        {
            cplx u = x[b0], v = x[b0 + 2];
            x[b0]     = cadd(u, v);
            x[b0 + 2] = cmulc(csub(u, v), wb0);
        }
        {
            cplx u = x[b0 + 1], v = x[b0 + 3];
            x[b0 + 1] = cadd(u, v);
            x[b0 + 3] = cmulc(csub(u, v), wb1);
        }
    }
    // stage 3'
    cplx wa = t128[8 * j];
#pragma unroll
    for (int t = 0; t < 16; t += 2) {
        cplx u = x[t], v = x[t + 1];
        x[t]     = cadd(u, v);
        x[t + 1] = cmulc(csub(u, v), wa);
    }
}

// ---------------------------------------------------------------------------
// Kernel 2: z = y1 + i*y2, Z = FFT_16000 (128x125 four-step), Hermitian split
// + pointwise multiply, phi = Re(IFFT)/N.  float2 interleaved shared storage.
// Radix-2 column FFT = radix-8 pass + radix-16 pass (with inter-phase twiddle
// fused into the radix-16 pass).
// ---------------------------------------------------------------------------
__global__ void __launch_bounds__(THREADS)
mcb_fft_kernel(const float* __restrict__ x1, const float* __restrict__ x2,
               float* __restrict__ out) {
    extern __shared__ cplx S[];                // 16000 complex = 128000 B
    __shared__ cplx t128[128];                 // e^{-2pi i t/128}
    __shared__ cplx t125[125];                 // e^{-2pi i t/125}
    __shared__ cplx tS[125];                   // e^{-2pi i t/16000}

    const int tid = threadIdx.x;
    const int b   = blockIdx.x;
    const double TWO_PI = 6.283185307179586476925286766559;

    for (int t = tid; t < 128; t += THREADS) {
        double s, c; sincos(-TWO_PI * (double)t / 128.0, &s, &c);
        t128[t] = make_float2((float)c, (float)s);
    }
    for (int t = tid; t < 125; t += THREADS) {
        double s, c;
        sincos(-TWO_PI * (double)t / 125.0, &s, &c);
        t125[t] = make_float2((float)c, (float)s);
        sincos(-TWO_PI * (double)t / 16000.0, &s, &c);
        tS[t] = make_float2((float)c, (float)s);
    }
    for (int i = tid; i < P_DIM; i += THREADS) S[i] = make_float2(0.0f, 0.0f);
    __syncthreads();

    // scatter: y1 -> real, y2 -> imag, rows bit-reversed for the DIT stages
    for (int d = tid; d < D_DIM; d += THREADS) {
        int p = g_idx[d];
        float v = x1[b * D_DIM + d] * g_sgn[d];
        int n1 = p / 125, n2 = p - n1 * 125;
        int r = __brev(n1) >> 25;
        atomicAdd(&S[r * 125 + n2].x, v);
        p = g_idx[D_DIM + d];
        v = x2[b * D_DIM + d] * g_sgn[D_DIM + d];
        n1 = p / 125; n2 = p - n1 * 125;
        r = __brev(n1) >> 25;
        atomicAdd(&S[r * 125 + n2].y, v);
    }
    __syncthreads();

    // ---- forward radix-2 stages 0..2 (rows 8g+t, fixed col) ----
    for (int idx = tid; idx < 2000; idx += THREADS) {
        int c = idx % 125;
        int g = idx / 125;
        int base = g * 1000 + c;
        cplx x[8];
#pragma unroll
        for (int t = 0; t < 8; t++) x[t] = S[base + t * 125];
        radix8_dit(x, 0, t128);
#pragma unroll
        for (int t = 0; t < 8; t++) S[base + t * 125] = x[t];
    }
    __syncthreads();

    // ---- forward radix-2 stages 3..6 + inter-phase twiddle (radix-16) ----
    if (tid < 1000) {
        int c = tid % 125;
        int j = tid / 125;        // 0..7
        int base = j * 125 + c;
        cplx x[16];
#pragma unroll
        for (int t = 0; t < 16; t++) x[t] = S[base + t * 1000];
        radix16_dit(x, j, t128);
#pragma unroll
        for (int t = 0; t < 16; t++) {
            int k1 = j + 8 * t;
            int mm = c * k1;
            int q = mm / 125, rr = mm - q * 125;
            S[base + t * 1000] = cmul(x[t], cmul(t128[q], tS[rr]));
        }
    }
    __syncthreads();

    // ---- forward: 3 radix-5 DIF stages (length-125 row FFTs) ----
    const float C72  =  0.30901699437494742f, S72  = 0.95105651629515357f;
    const float C144 = -0.80901699437494745f, S144 = 0.58778525229247314f;
#pragma unroll
    for (int sidx = 0; sidx < 3; sidx++) {
        const int L = (sidx == 0) ? 125 : (sidx == 1) ? 25 : 5;
        const int m = L / 5;
        const int f = 125 / L;
        for (int idx = tid; idx < 3200; idx += THREADS) {
            int r  = idx & 127;
            int bj = idx >> 7;
            int j  = bj % m;
            int base = r * 125 + (bj / m) * L + j;
            cplx a0 = S[base];
            cplx a1 = S[base + m];
            cplx a2 = S[base + 2 * m];
            cplx a3 = S[base + 3 * m];
            cplx a4 = S[base + 4 * m];
            cplx t1 = cadd(a1, a4), t3 = csub(a1, a4);
            cplx t2 = cadd(a2, a3), t4 = csub(a2, a3);
            cplx y0 = make_float2(a0.x + t1.x + t2.x, a0.y + t1.y + t2.y);
            cplx m1 = make_float2(a0.x + C72 * t1.x + C144 * t2.x,
                                  a0.y + C72 * t1.y + C144 * t2.y);
            cplx m2 = make_float2(a0.x + C144 * t1.x + C72 * t2.x,
                                  a0.y + C144 * t1.y + C72 * t2.y);
            cplx v1 = make_float2(S72 * t3.x + S144 * t4.x, S72 * t3.y + S144 * t4.y);
            cplx v2 = make_float2(S144 * t3.x - S72 * t4.x, S144 * t3.y - S72 * t4.y);
            cplx y1 = make_float2(m1.x + v1.y, m1.y - v1.x);
            cplx y2 = make_float2(m2.x + v2.y, m2.y - v2.x);
            cplx y3 = make_float2(m2.x - v2.y, m2.y + v2.x);
            cplx y4 = make_float2(m1.x - v1.y, m1.y + v1.x);
            int jf = j * f;
            S[base]         = y0;
            S[base + m]     = cmul(y1, t125[jf]);
            S[base + 2 * m] = cmul(y2, t125[2 * jf]);
            S[base + 3 * m] = cmul(y3, t125[3 * jf]);
            S[base + 4 * m] = cmul(y4, t125[4 * jf]);
        }
        __syncthreads();
    }

    // ---- Hermitian split + pointwise multiply, in scrambled storage ----
    for (int k = tid; k <= 8000; k += THREADS) {
        if (k == 0) {
            cplx z = S[0];
            S[0] = make_float2(z.x * z.y, 0.0f);
        } else if (k == 8000) {
            const int addr = 64 * 125 + 62;
            cplx z = S[addr];
            S[addr] = make_float2(z.x * z.y, 0.0f);
        } else {
            int k1 = k & 127, k2 = k >> 7;
            int pa = k1 * 125 + dr5(k2);
            int kp = P_DIM - k;
            int k1p = kp & 127, k2p = kp >> 7;
            int pb = k1p * 125 + dr5(k2p);
            cplx A = S[pa];
            cplx Bv = S[pb];
            float F1r = 0.5f * (A.x + Bv.x), F1i = 0.5f * (A.y - Bv.y);
            float F2r = 0.5f * (A.y + Bv.y), F2i = 0.5f * (Bv.x - A.x);
            float Hr = F1r * F2r - F1i * F2i;
            float Hi = F1r * F2i + F1i * F2r;
            S[pa] = make_float2(Hr,  Hi);
            S[pb] = make_float2(Hr, -Hi);
        }
    }
    __syncthreads();

    // ---- inverse: 3 radix-5 DIT stages (rows), conj twiddles ----
#pragma unroll
    for (int sidx = 0; sidx < 3; sidx++) {
        const int L = (sidx == 0) ? 5 : (sidx == 1) ? 25 : 125;
        const int m = L / 5;
        const int f = 125 / L;
        for (int idx = tid; idx < 3200; idx += THREADS) {
            int r  = idx & 127;
            int bj = idx >> 7;
            int j  = bj % m;
            int base = r * 125 + (bj / m) * L + j;
            int jf = j * f;
            cplx a0 = S[base];
            cplx a1 = cmulc(S[base + m],     t125[jf]);
            cplx a2 = cmulc(S[base + 2 * m], t125[2 * jf]);
            cplx a3 = cmulc(S[base + 3 * m], t125[3 * jf]);
            cplx a4 = cmulc(S[base + 4 * m], t125[4 * jf]);
            cplx t1 = cadd(a1, a4), t3 = csub(a1, a4);
            cplx t2 = cadd(a2, a3), t4 = csub(a2, a3);
            cplx y0 = make_float2(a0.x + t1.x + t2.x, a0.y + t1.y + t2.y);
            cplx m1 = make_float2(a0.x + C72 * t1.x + C144 * t2.x,
                                  a0.y + C72 * t1.y + C144 * t2.y);
            cplx m2 = make_float2(a0.x + C144 * t1.x + C72 * t2.x,
                                  a0.y + C144 * t1.y + C72 * t2.y);
            cplx v1 = make_float2(S72 * t3.x + S144 * t4.x, S72 * t3.y + S144 * t4.y);
            cplx v2 = make_float2(S144 * t3.x - S72 * t4.x, S144 * t3.y - S72 * t4.y);
            S[base]         = y0;
            S[base + m]     = make_float2(m1.x - v1.y, m1.y + v1.x);
            S[base + 2 * m] = make_float2(m2.x - v2.y, m2.y + v2.x);
            S[base + 3 * m] = make_float2(m2.x + v2.y, m2.y - v2.x);
            S[base + 4 * m] = make_float2(m1.x + v1.y, m1.y - v1.x);
        }
        __syncthreads();
    }

    // ---- inverse inter-phase twiddle (conj) + radix-2 stages 6..3 (radix-16) ----
    if (tid < 1000) {
        int c = tid % 125;
        int j = tid / 125;
        int base = j * 125 + c;
        cplx x[16];
#pragma unroll
        for (int t = 0; t < 16; t++) {
            int k1 = j + 8 * t;
            int mm = c * k1;
            int q = mm / 125, rr = mm - q * 125;
            x[t] = cmulc(S[base + t * 1000], cmul(t128[q], tS[rr]));
        }
        radix16_dif(x, j, t128);
#pragma unroll
        for (int t = 0; t < 16; t++) S[base + t * 1000] = x[t];
    }
    __syncthreads();

    // ---- inverse radix-2 stages 2..0, fused with output write ----
    const float scale = 1.0f / 16000.0f;
    for (int idx = tid; idx < 2000; idx += THREADS) {
        int c = idx % 125;
        int g = idx / 125;
        int base = g * 1000 + c;
        cplx x[8];
#pragma unroll
        for (int t = 0; t < 8; t++) x[t] = S[base + t * 125];
        radix8_dif(x, 0, t128);
#pragma unroll
        for (int t = 0; t < 8; t++) {
            int n1 = __brev(8 * g + t) >> 25;
            out[b * P_DIM + n1 * 125 + c] = x[t].x * scale;
        }
    }
}

extern "C" void kernel_launch(void* const* d_in, const int* in_sizes, int n_in,
                              void* d_out, int out_size) {
    const float* x1 = (const float*)d_in[0];
    const float* x2 = (const float*)d_in[1];
    const float* C1 = (const float*)d_in[2];
    const float* C2 = (const float*)d_in[3];
    float* out = (float*)d_out;

    extract_kernel<<<2 * D_DIM, EX_THREADS>>>(C1, C2);

    const size_t smem = (size_t)P_DIM * sizeof(cplx);  // 128000 B
    cudaFuncSetAttribute(mcb_fft_kernel,
                         cudaFuncAttributeMaxDynamicSharedMemorySize, (int)smem);
    mcb_fft_kernel<<<B_BATCH, THREADS, smem>>>(x1, x2, out);
}